// round 2
// baseline (speedup 1.0000x reference)
#include <cuda_runtime.h>
#include <cstdint>

// Problem constants (fixed by the dataset)
#define NN   10000
#define EE   320000
#define BB   2
#define CINN 64
#define HID  128
#define COUT 128
#define TE   256          // edges per block in the edge kernel
#define HSTR 260          // padded h-tile k-row stride (banks: 4k+m -> no p-group conflict)

// Scratch (device globals: no allocations allowed)
__device__ float g_a_dst[(size_t)NN * HID];        //  5.12 MB
__device__ float g_a_src[(size_t)BB * NN * HID];   // 10.24 MB
__device__ float g_agg  [(size_t)BB * NN * HID];   // 10.24 MB (weighted h2 aggregate)
__device__ float g_den  [NN];

typedef unsigned long long u64;

__device__ __forceinline__ float gelu_f(float v) {
    return 0.5f * v * (1.0f + erff(v * 0.70710678118654752440f));
}
__device__ __forceinline__ u64 pack2(float a) {
    u64 r; asm("mov.b64 %0, {%1, %1};" : "=l"(r) : "f"(a)); return r;
}
__device__ __forceinline__ void ffma2(u64& d, u64 a, u64 b) {
    asm("fma.rn.f32x2 %0, %1, %2, %0;" : "+l"(d) : "l"(a), "l"(b));
}
__device__ __forceinline__ float2 unpack2(u64 v) {
    float2 f; asm("mov.b64 {%0, %1}, %2;" : "=f"(f.x), "=f"(f.y) : "l"(v)); return f;
}

// ---------------------------------------------------------------------------
// den[n] = sum of edge_weights into dst n
// ---------------------------------------------------------------------------
__global__ void den_kernel(const int* __restrict__ eidx, const float* __restrict__ ew) {
    const int e = blockIdx.x * blockDim.x + threadIdx.x;
    if (e < EE) atomicAdd(&g_den[eidx[EE + e]], ew[e]);
}

// ---------------------------------------------------------------------------
// Per-node precompute (also zeroes g_agg / g_den — fused zero kernel):
//   a_dst[n]   = pos[n] @ W1[0:3]
//   a_src[b,n] = pos[n] @ W1[3:6] + x[b,n] @ W1[6:70] + b1
//   out[b,n]   = x[b,n] @ Ws + bs   (skip path, written first; final adds)
// One block per (b,n), 128 threads (thread = output channel).
// ---------------------------------------------------------------------------
__global__ void precompute_kernel(const float* __restrict__ x, const float* __restrict__ pos,
                                  const float* __restrict__ W1, const float* __restrict__ b1,
                                  const float* __restrict__ Ws, const float* __restrict__ bs,
                                  float* __restrict__ out) {
    const int blk = blockIdx.x;          // b*NN + n
    const int b   = blk / NN;
    const int n   = blk - b * NN;
    const int t   = threadIdx.x;         // 0..127
    __shared__ float xr[CINN];
    __shared__ float p3[3];
    if (t < CINN) xr[t] = x[(size_t)blk * CINN + t];
    if (t < 3)    p3[t] = pos[n * 3 + t];

    g_agg[(size_t)blk * HID + t] = 0.0f;         // fused zero of aggregate
    if (b == 0 && t == 0) g_den[n] = 0.0f;       // fused zero of denominator
    __syncthreads();

    float s = b1[t];
#pragma unroll
    for (int j = 0; j < 3; ++j) s += p3[j] * W1[(3 + j) * HID + t];
#pragma unroll 8
    for (int c = 0; c < CINN; ++c) s += xr[c] * W1[(6 + c) * HID + t];
    g_a_src[(size_t)blk * HID + t] = s;

    if (b == 0) {
        float d = p3[0] * W1[0 * HID + t] + p3[1] * W1[1 * HID + t] + p3[2] * W1[2 * HID + t];
        g_a_dst[(size_t)n * HID + t] = d;
    }

    float sk = bs[t];
#pragma unroll 8
    for (int c = 0; c < CINN; ++c) sk += xr[c] * Ws[c * COUT + t];
    out[(size_t)blk * COUT + t] = sk;
}

// ---------------------------------------------------------------------------
// Edge kernel: per tile of TE=256 edges (x batch):
//   h1 = gelu(a_dst[dst] + a_src[b,src])         (filled transposed [k][m] in smem)
//   acc = h1 @ W2                                 (register-tiled, f32x2 FFMA)
//   s[b,dst] += w_e * gelu(acc + b2)              (red.global.add.v4.f32)
// 512 threads (16 warps -> 4/SMSP for latency hiding); thread tile 8x8.
// smem = h tile [128][260] (133120 B) + W2 [128][128] (65536 B) = 198656 B.
// ---------------------------------------------------------------------------
__global__ void __launch_bounds__(512, 1)
edge_kernel(const int* __restrict__ eidx, const float* __restrict__ ew,
            const float* __restrict__ W2, const float* __restrict__ b2) {
    extern __shared__ float sm[];
    float* h_s = sm;                   // [128][HSTR]  h1 transposed: h_s[k][m]
    float* w_s = sm + HID * HSTR;      // [128][128]   W2[k][n]
    const int tid = threadIdx.x;
    const int e0  = blockIdx.x * TE;
    const int b   = blockIdx.y;
    const int* __restrict__ srcp = eidx;
    const int* __restrict__ dstp = eidx + EE;

    // Stage W2 (16384 floats = 4096 float4, 512 threads -> 8 each, coalesced)
    {
        const float4* w4 = (const float4*)W2;
        float4* s4 = (float4*)w_s;
#pragma unroll
        for (int i = 0; i < 8; ++i) s4[tid + i * 512] = w4[tid + i * 512];
    }

    // Fill h1 tile transposed. Each warp owns 16 edges; lane pairs split k so
    // a pair reads contiguous 32B from the same row (full-sector gathers).
    {
        const int w = tid >> 5, l = tid & 31;
        const int m = w * 16 + (l >> 1);
        const int e = e0 + m;
        const int s = srcp[e];
        const int d = dstp[e];
        const float4* pd4 = (const float4*)(g_a_dst + (size_t)d * HID);
        const float4* ps4 = (const float4*)(g_a_src + ((size_t)b * NN + s) * HID);
        const int p = l & 1;
#pragma unroll
        for (int k8 = 0; k8 < 16; ++k8) {
            const int kq = k8 * 2 + p;         // float4 index along k
            float4 A  = pd4[kq];
            float4 Bv = ps4[kq];
            const int k = kq * 4;
            h_s[(k + 0) * HSTR + m] = gelu_f(A.x + Bv.x);
            h_s[(k + 1) * HSTR + m] = gelu_f(A.y + Bv.y);
            h_s[(k + 2) * HSTR + m] = gelu_f(A.z + Bv.z);
            h_s[(k + 3) * HSTR + m] = gelu_f(A.w + Bv.w);
        }
    }
    __syncthreads();

    // Register-tiled GEMM: thread (tm,tn) computes edges tm*8..+7,
    // cols {tn*4..+3} and {64+tn*4..+3}. A-reads broadcast within warp.
    const int tn = tid & 15;
    const int tm = tid >> 4;          // 0..31
    u64 acc[8][4];
#pragma unroll
    for (int i = 0; i < 8; ++i)
#pragma unroll
        for (int g = 0; g < 4; ++g) acc[i][g] = 0ull;

#pragma unroll 4
    for (int k = 0; k < 128; ++k) {
        const float* hr = h_s + k * HSTR + tm * 8;
        const float4 A0 = *(const float4*)hr;
        const float4 A1 = *(const float4*)(hr + 4);
        const float* wr = w_s + k * HID + tn * 4;
        const ulonglong2 B0 = *(const ulonglong2*)wr;          // n = tn*4 .. +3
        const ulonglong2 B1 = *(const ulonglong2*)(wr + 64);   // n = 64+tn*4 .. +3
        const float av[8] = {A0.x, A0.y, A0.z, A0.w, A1.x, A1.y, A1.z, A1.w};
#pragma unroll
        for (int i = 0; i < 8; ++i) {
            const u64 a2 = pack2(av[i]);
            ffma2(acc[i][0], a2, B0.x);
            ffma2(acc[i][1], a2, B0.y);
            ffma2(acc[i][2], a2, B1.x);
            ffma2(acc[i][3], a2, B1.y);
        }
    }

    // Epilogue: gelu(acc + b2) * w_e, 16B vector reductions into g_agg
    const float4 b2v0 = *(const float4*)(b2 + tn * 4);
    const float4 b2v1 = *(const float4*)(b2 + 64 + tn * 4);
#pragma unroll
    for (int i = 0; i < 8; ++i) {
        const int m = tm * 8 + i;
        const int e = e0 + m;
        const float wgt = ew[e];
        const int d = dstp[e];
        float* base = g_agg + ((size_t)b * NN + d) * HID;
        {
            const float2 v0 = unpack2(acc[i][0]);
            const float2 v1 = unpack2(acc[i][1]);
            const float r0 = wgt * gelu_f(v0.x + b2v0.x);
            const float r1 = wgt * gelu_f(v0.y + b2v0.y);
            const float r2 = wgt * gelu_f(v1.x + b2v0.z);
            const float r3 = wgt * gelu_f(v1.y + b2v0.w);
            asm volatile("red.global.add.v4.f32 [%0], {%1,%2,%3,%4};"
                         :: "l"(base + tn * 4), "f"(r0), "f"(r1), "f"(r2), "f"(r3)
                         : "memory");
        }
        {
            const float2 v0 = unpack2(acc[i][2]);
            const float2 v1 = unpack2(acc[i][3]);
            const float r0 = wgt * gelu_f(v0.x + b2v1.x);
            const float r1 = wgt * gelu_f(v0.y + b2v1.y);
            const float r2 = wgt * gelu_f(v1.x + b2v1.z);
            const float r3 = wgt * gelu_f(v1.y + b2v1.w);
            asm volatile("red.global.add.v4.f32 [%0], {%1,%2,%3,%4};"
                         :: "l"(base + 64 + tn * 4), "f"(r0), "f"(r1), "f"(r2), "f"(r3)
                         : "memory");
        }
    }
}

// ---------------------------------------------------------------------------
// Final: out[b,n] += (s[b,n] @ W3 + den[n]*b3) / (den[n] + eps)
// Tiled: 16 (b,n)-rows per block, 256 threads, W3 staged in smem (64KB) so
// the weight reads are smem broadcasts instead of 10M warp-LDGs.
// ---------------------------------------------------------------------------
__global__ void __launch_bounds__(256, 1)
final_kernel(const float* __restrict__ W3, const float* __restrict__ b3,
             float* __restrict__ out) {
    extern __shared__ float fs[];
    float* W3s = fs;               // [128][128]
    float* s_s = fs + HID * COUT;  // [16][128]
    const int tid = threadIdx.x;
    const int r0  = blockIdx.x * 16;   // first (b*NN+n) row of this tile

    // Stage W3 (4096 float4 / 256 threads = 16 each)
    {
        const float4* w4 = (const float4*)W3;
        float4* s4 = (float4*)W3s;
#pragma unroll
        for (int i = 0; i < 16; ++i) s4[tid + i * 256] = w4[tid + i * 256];
    }
    // Stage the 16 aggregate rows (512 float4 / 256 threads = 2 each)
    {
        const float4* a4 = (const float4*)(g_agg + (size_t)r0 * HID);
        float4* s4 = (float4*)s_s;
#pragma unroll
        for (int i = 0; i < 2; ++i) s4[tid + i * 256] = a4[tid + i * 256];
    }
    __syncthreads();

    const int tm  = tid >> 4;          // row within tile, 0..15
    const int tn  = tid & 15;          // col group *8
    const int row = r0 + tm;           // b*NN + n
    const int n   = row % NN;
    const float den = g_den[n];

    float acc[8];
#pragma unroll
    for (int j = 0; j < 8; ++j) acc[j] = den * b3[tn * 8 + j];

#pragma unroll 8
    for (int k = 0; k < 128; ++k) {
        const float a = s_s[tm * HID + k];
        const float4 B0 = *(const float4*)(W3s + k * COUT + tn * 8);
        const float4 B1 = *(const float4*)(W3s + k * COUT + tn * 8 + 4);
        acc[0] += a * B0.x; acc[1] += a * B0.y; acc[2] += a * B0.z; acc[3] += a * B0.w;
        acc[4] += a * B1.x; acc[5] += a * B1.y; acc[6] += a * B1.z; acc[7] += a * B1.w;
    }

    const float inv = 1.0f / (den + 1e-12f);
    float* op = out + (size_t)row * COUT + tn * 8;
#pragma unroll
    for (int j = 0; j < 8; ++j) op[j] += acc[j] * inv;
}

// ---------------------------------------------------------------------------
extern "C" void kernel_launch(void* const* d_in, const int* in_sizes, int n_in,
                              void* d_out, int out_size) {
    const float* x   = (const float*)d_in[0];
    const float* pos = (const float*)d_in[1];
    const int*   ei  = (const int*)  d_in[2];
    const float* ew  = (const float*)d_in[3];
    const float* W1  = (const float*)d_in[4];
    const float* b1  = (const float*)d_in[5];
    const float* W2  = (const float*)d_in[6];
    const float* b2  = (const float*)d_in[7];
    const float* W3  = (const float*)d_in[8];
    const float* b3  = (const float*)d_in[9];
    const float* Ws  = (const float*)d_in[10];
    const float* bs  = (const float*)d_in[11];
    float* out = (float*)d_out;

    const int edge_smem  = (HID * HSTR + HID * HID) * (int)sizeof(float);  // 198656
    const int final_smem = (HID * COUT + 16 * HID) * (int)sizeof(float);   //  73728
    cudaFuncSetAttribute(edge_kernel,  cudaFuncAttributeMaxDynamicSharedMemorySize, edge_smem);
    cudaFuncSetAttribute(final_kernel, cudaFuncAttributeMaxDynamicSharedMemorySize, final_smem);

    precompute_kernel<<<BB * NN, HID>>>(x, pos, W1, b1, Ws, bs, out);
    den_kernel<<<(EE + 255) / 256, 256>>>(ei, ew);
    edge_kernel<<<dim3(EE / TE, BB), 512, edge_smem>>>(ei, ew, W2, b2);
    final_kernel<<<(BB * NN) / 16, 256, final_smem>>>(W3, b3, out);
}

// round 4
// speedup vs baseline: 1.1999x; 1.1999x over previous
#include <cuda_runtime.h>
#include <cstdint>

// Problem constants (fixed by the dataset)
#define NN   10000
#define EE   320000
#define BB   2
#define CINN 64
#define HID  128
#define COUT 128
#define TE   128          // edges per block (= M tile of the edge GEMM)

// Scratch (device globals: no allocations allowed)
__device__ float    g_a_dst[(size_t)NN * HID];        //  5.12 MB
__device__ float    g_a_src[(size_t)BB * NN * HID];   // 10.24 MB
__device__ float    g_agg  [(size_t)BB * NN * HID];   // 10.24 MB
__device__ float    g_den  [NN];
__device__ uint32_t g_W2p  [2 * HID * HID];           // W2 as tf32 b-fragments (64KB)

__device__ __forceinline__ float gelu_f(float v) {
    return 0.5f * v * (1.0f + erff(v * 0.70710678118654752440f));
}
__device__ __forceinline__ uint32_t f2tf32(float f) {
    uint32_t r; asm("cvt.rna.tf32.f32 %0, %1;" : "=r"(r) : "f"(f)); return r;
}
// mma.sync m16n8k8 tf32 (A row-major frag, B col-major frag, f32 accum)
__device__ __forceinline__ void mma_tf32(float* d, const uint32_t* a, const uint32_t* b) {
    asm volatile("mma.sync.aligned.m16n8k8.row.col.f32.tf32.tf32.f32 "
                 "{%0,%1,%2,%3}, {%4,%5,%6,%7}, {%8,%9}, {%0,%1,%2,%3};"
                 : "+f"(d[0]), "+f"(d[1]), "+f"(d[2]), "+f"(d[3])
                 : "r"(a[0]), "r"(a[1]), "r"(a[2]), "r"(a[3]), "r"(b[0]), "r"(b[1]));
}

// ---------------------------------------------------------------------------
// One-time prep: pack W2 (HIDxCOUT row-major) into tf32 B fragments.
// Fragment entry (t, s, l, j):  t = n8 tile (0..15), s = k8 step (0..15),
// l = lane, j = 0/1 -> b0/b1.  b_j = W2[k = 8s + 4j + (l&3)][n = 8t + (l>>2)].
// ---------------------------------------------------------------------------
__global__ void w2prep_kernel(const float* __restrict__ W2) {
    const int idx = blockIdx.x * blockDim.x + threadIdx.x;   // 0..32767
    const int j = idx & 1;
    const int l = (idx >> 1) & 31;
    const int s = (idx >> 6) & 15;
    const int t = idx >> 10;
    const int k = s * 8 + j * 4 + (l & 3);
    const int n = t * 8 + (l >> 2);
    g_W2p[idx] = f2tf32(W2[k * HID + n]);
}

// ---------------------------------------------------------------------------
// den[n] = sum of edge_weights into dst n
// ---------------------------------------------------------------------------
__global__ void den_kernel(const int* __restrict__ eidx, const float* __restrict__ ew) {
    const int e = blockIdx.x * blockDim.x + threadIdx.x;
    if (e < EE) atomicAdd(&g_den[eidx[EE + e]], ew[e]);
}

// ---------------------------------------------------------------------------
// Per-node precompute (also zeroes g_agg / g_den):
//   a_dst[n]   = pos[n] @ W1[0:3]
//   a_src[b,n] = pos[n] @ W1[3:6] + x[b,n] @ W1[6:70] + b1
//   out[b,n]   = x[b,n] @ Ws + bs   (skip path; final adds)
// ---------------------------------------------------------------------------
__global__ void precompute_kernel(const float* __restrict__ x, const float* __restrict__ pos,
                                  const float* __restrict__ W1, const float* __restrict__ b1,
                                  const float* __restrict__ Ws, const float* __restrict__ bs,
                                  float* __restrict__ out) {
    const int blk = blockIdx.x;          // b*NN + n
    const int b   = blk / NN;
    const int n   = blk - b * NN;
    const int t   = threadIdx.x;         // 0..127
    __shared__ float xr[CINN];
    __shared__ float p3[3];
    if (t < CINN) xr[t] = x[(size_t)blk * CINN + t];
    if (t < 3)    p3[t] = pos[n * 3 + t];

    g_agg[(size_t)blk * HID + t] = 0.0f;
    if (b == 0 && t == 0) g_den[n] = 0.0f;
    __syncthreads();

    float s = b1[t];
#pragma unroll
    for (int j = 0; j < 3; ++j) s += p3[j] * W1[(3 + j) * HID + t];
#pragma unroll 8
    for (int c = 0; c < CINN; ++c) s += xr[c] * W1[(6 + c) * HID + t];
    g_a_src[(size_t)blk * HID + t] = s;

    if (b == 0) {
        float d = p3[0] * W1[0 * HID + t] + p3[1] * W1[1 * HID + t] + p3[2] * W1[2 * HID + t];
        g_a_dst[(size_t)n * HID + t] = d;
    }

    float sk = bs[t];
#pragma unroll 8
    for (int c = 0; c < CINN; ++c) sk += xr[c] * Ws[c * COUT + t];
    out[(size_t)blk * COUT + t] = sk;
}

// ---------------------------------------------------------------------------
// Edge kernel (mma.sync tf32). Per block: 128 edges, 256 threads (8 warps).
//   fill:  h1[m][k] = tf32(gelu(a_dst[dst]+a_src[b,src])) packed as A frags
//   GEMM:  warp (wm,wn) computes D tile m[32] x n[64]; 16 k-steps
//   epi:   w_e * gelu(D + b2) -> red.global.add.v2.f32 into g_agg[b,dst]
// SMEM: A frags 64KB | B frags 64KB | b2/ew/dst staging. 1 block/SM.
// ---------------------------------------------------------------------------
#define EDGE_SMEM (65536 + 65536 + 512 + 512 + 512)
__global__ void __launch_bounds__(256, 1)
edge_kernel(const int* __restrict__ eidx, const float* __restrict__ ew,
            const float* __restrict__ b2) {
    extern __shared__ char sm[];
    uint32_t* A_s  = (uint32_t*)sm;                 // [8 g][16 s][32 l][4 slot]
    uint32_t* B_s  = (uint32_t*)(sm + 65536);       // [16 t][16 s][32 l][2 j]
    float*    b2s  = (float*)   (sm + 131072);
    float*    ews  = (float*)   (sm + 131584);
    int*      dsts = (int*)     (sm + 132096);
    const int tid = threadIdx.x;
    const int e0  = blockIdx.x * TE;
    const int b   = blockIdx.y;

    // Stage pre-packed W2 fragments (64KB linear float4 copy)
    {
        const float4* s4 = (const float4*)g_W2p;
        float4* d4 = (float4*)B_s;
#pragma unroll
        for (int i = 0; i < 16; ++i) d4[tid + i * 256] = s4[tid + i * 256];
    }
    if (tid < TE) {
        b2s[tid]  = b2[tid];
        ews[tid]  = ew[e0 + tid];
        dsts[tid] = eidx[EE + e0 + tid];
    }

    // Fill A fragments: 2 threads per edge (k halves). Edge row m:
    // frag coords: group g=m>>4, row-in-group r=m&15 -> lane l=(r&7)*4+(kk&3),
    // slot = (kk>=4)*2 + (r>=8).
    {
        const int m    = tid >> 1;
        const int half = tid & 1;
        const int sv   = eidx[e0 + m];
        const int dv   = eidx[EE + e0 + m];
        const int g    = m >> 4;
        const int r    = m & 15;
        const int lbase = (r & 7) * 4;
        const int rbit  = r >> 3;
        const float4* pd4 = (const float4*)(g_a_dst + (size_t)dv * HID);
        const float4* ps4 = (const float4*)(g_a_src + ((size_t)b * NN + sv) * HID);
#pragma unroll
        for (int si = 0; si < 8; ++si) {
            const int s = half * 8 + si;
            const float4 A0 = pd4[s * 2],     S0 = ps4[s * 2];
            const float4 A1 = pd4[s * 2 + 1], S1 = ps4[s * 2 + 1];
            float v[8] = {A0.x + S0.x, A0.y + S0.y, A0.z + S0.z, A0.w + S0.w,
                          A1.x + S1.x, A1.y + S1.y, A1.z + S1.z, A1.w + S1.w};
            uint32_t* bp = A_s + (g * 16 + s) * 128;
#pragma unroll
            for (int kk = 0; kk < 8; ++kk) {
                const int l    = lbase + (kk & 3);
                const int slot = ((kk >> 2) << 1) + rbit;
                bp[l * 4 + slot] = f2tf32(gelu_f(v[kk]));
            }
        }
    }
    __syncthreads();

    // GEMM: warp (wm, wn) -> edges [wm*32, +32), cols [wn*64, +64)
    const int lane = tid & 31;
    const int w    = tid >> 5;
    const int wm   = w & 3;
    const int wn   = w >> 2;
    float acc[2][8][4];
#pragma unroll
    for (int g = 0; g < 2; ++g)
#pragma unroll
        for (int t = 0; t < 8; ++t)
#pragma unroll
            for (int q = 0; q < 4; ++q) acc[g][t][q] = 0.0f;

#pragma unroll 2
    for (int s = 0; s < 16; ++s) {
        uint32_t a[2][4];
#pragma unroll
        for (int g = 0; g < 2; ++g) {
            const uint4 av = *(const uint4*)(A_s + ((wm * 2 + g) * 16 + s) * 128 + lane * 4);
            a[g][0] = av.x; a[g][1] = av.y; a[g][2] = av.z; a[g][3] = av.w;
        }
        uint32_t bf[8][2];
#pragma unroll
        for (int t = 0; t < 8; ++t) {
            const uint2 bv = *(const uint2*)(B_s + ((wn * 8 + t) * 16 + s) * 64 + lane * 2);
            bf[t][0] = bv.x; bf[t][1] = bv.y;
        }
#pragma unroll
        for (int g = 0; g < 2; ++g)
#pragma unroll
            for (int t = 0; t < 8; ++t) mma_tf32(acc[g][t], a[g], bf[t]);
    }

    // Epilogue: D frag (r = lane>>2 (+8), c = 2*(lane&3) (+1)) -> v2 reductions
#pragma unroll
    for (int g = 0; g < 2; ++g) {
#pragma unroll
        for (int rh = 0; rh < 2; ++rh) {
            const int m   = wm * 32 + g * 16 + rh * 8 + (lane >> 2);
            const float wgt = ews[m];
            float* base = g_agg + ((size_t)b * NN + dsts[m]) * HID;
#pragma unroll
            for (int t = 0; t < 8; ++t) {
                const int c = wn * 64 + t * 8 + (lane & 3) * 2;
                const float r0 = wgt * gelu_f(acc[g][t][rh * 2 + 0] + b2s[c]);
                const float r1 = wgt * gelu_f(acc[g][t][rh * 2 + 1] + b2s[c + 1]);
                asm volatile("red.global.add.v2.f32 [%0], {%1,%2};"
                             :: "l"(base + c), "f"(r0), "f"(r1) : "memory");
            }
        }
    }
}

// ---------------------------------------------------------------------------
// Final: out[b,n] += (s[b,n] @ W3 + den[n]*b3) / (den[n] + eps)
// One block per (b,n); 128 threads; W3 stays L1-resident (64 KB).
// ---------------------------------------------------------------------------
__global__ void final_kernel(const float* __restrict__ W3, const float* __restrict__ b3,
                             float* __restrict__ out) {
    __shared__ float s_s[HID];
    const int blk = blockIdx.x;       // b*NN + n
    const int n   = blk % NN;
    const int c   = threadIdx.x;
    s_s[c] = g_agg[(size_t)blk * HID + c];
    __syncthreads();
    const float den = g_den[n];
    float acc = den * b3[c];
#pragma unroll 8
    for (int k = 0; k < HID; ++k) acc += s_s[k] * W3[k * COUT + c];
    out[(size_t)blk * COUT + c] += acc / (den + 1e-12f);
}

// ---------------------------------------------------------------------------
extern "C" void kernel_launch(void* const* d_in, const int* in_sizes, int n_in,
                              void* d_out, int out_size) {
    const float* x   = (const float*)d_in[0];
    const float* pos = (const float*)d_in[1];
    const int*   ei  = (const int*)  d_in[2];
    const float* ew  = (const float*)d_in[3];
    const float* W1  = (const float*)d_in[4];
    const float* b1  = (const float*)d_in[5];
    const float* W2  = (const float*)d_in[6];
    const float* b2  = (const float*)d_in[7];
    const float* W3  = (const float*)d_in[8];
    const float* b3  = (const float*)d_in[9];
    const float* Ws  = (const float*)d_in[10];
    const float* bs  = (const float*)d_in[11];
    float* out = (float*)d_out;

    cudaFuncSetAttribute(edge_kernel, cudaFuncAttributeMaxDynamicSharedMemorySize, EDGE_SMEM);

    w2prep_kernel<<<2 * HID * HID / 256, 256>>>(W2);
    precompute_kernel<<<BB * NN, HID>>>(x, pos, W1, b1, Ws, bs, out);
    den_kernel<<<(EE + 255) / 256, 256>>>(ei, ew);
    edge_kernel<<<dim3(EE / TE, BB), 256, EDGE_SMEM>>>(ei, ew, b2);
    final_kernel<<<BB * NN, HID>>>(W3, b3, out);
}

// round 5
// speedup vs baseline: 1.3669x; 1.1391x over previous
#include <cuda_runtime.h>
#include <cstdint>

// Problem constants (fixed by the dataset)
#define NN   10000
#define EE   320000
#define BB   2
#define CINN 64
#define HID  128
#define COUT 128
#define TE   128          // edges per block (= M tile of the edge GEMM)

// Scratch (device globals: no allocations allowed)
__device__ float    g_a_dst[(size_t)NN * HID];        //  5.12 MB
__device__ float    g_a_src[(size_t)BB * NN * HID];   // 10.24 MB
__device__ float    g_agg  [(size_t)BB * NN * HID];   // 10.24 MB
__device__ float    g_den  [NN];
__device__ uint32_t g_W2p  [16 * 16 * 32 * 2];        // W2 tf32 b-fragments (64KB)

__device__ __forceinline__ float gelu_f(float v) {
    return 0.5f * v * (1.0f + erff(v * 0.70710678118654752440f));
}
__device__ __forceinline__ uint32_t f2tf32(float f) {
    uint32_t r; asm("cvt.rna.tf32.f32 %0, %1;" : "=r"(r) : "f"(f)); return r;
}
// mma.sync m16n8k8 tf32 (A row-major frag, B col-major frag, f32 accum)
__device__ __forceinline__ void mma_tf32(float* d, const uint32_t* a, const uint32_t* b) {
    asm volatile("mma.sync.aligned.m16n8k8.row.col.f32.tf32.tf32.f32 "
                 "{%0,%1,%2,%3}, {%4,%5,%6,%7}, {%8,%9}, {%0,%1,%2,%3};"
                 : "+f"(d[0]), "+f"(d[1]), "+f"(d[2]), "+f"(d[3])
                 : "r"(a[0]), "r"(a[1]), "r"(a[2]), "r"(a[3]), "r"(b[0]), "r"(b[1]));
}

// ---------------------------------------------------------------------------
// One-time prep: pack W2 (HIDxCOUT row-major) into tf32 B fragments.
// Entry (t, s, l, j): t = n8 tile, s = k8 step, l = lane, j = b0/b1.
//   b_j = W2[k = 8s + 4j + (l&3)][n = 8t + (l>>2)]
// ---------------------------------------------------------------------------
__global__ void w2prep_kernel(const float* __restrict__ W2) {
    const int idx = blockIdx.x * blockDim.x + threadIdx.x;   // 0..16383
    const int j = idx & 1;
    const int l = (idx >> 1) & 31;
    const int s = (idx >> 6) & 15;
    const int t = idx >> 10;                                  // 0..15
    const int k = s * 8 + j * 4 + (l & 3);
    const int n = t * 8 + (l >> 2);
    g_W2p[idx] = f2tf32(W2[k * HID + n]);
}

// ---------------------------------------------------------------------------
// Per-node precompute (also zeroes g_agg / g_den):
//   a_dst[n]   = pos[n] @ W1[0:3]
//   a_src[b,n] = pos[n] @ W1[3:6] + x[b,n] @ W1[6:70] + b1
//   out[b,n]   = x[b,n] @ Ws + bs   (skip path; final adds)
// ---------------------------------------------------------------------------
__global__ void precompute_kernel(const float* __restrict__ x, const float* __restrict__ pos,
                                  const float* __restrict__ W1, const float* __restrict__ b1,
                                  const float* __restrict__ Ws, const float* __restrict__ bs,
                                  float* __restrict__ out) {
    const int blk = blockIdx.x;          // b*NN + n
    const int b   = blk / NN;
    const int n   = blk - b * NN;
    const int t   = threadIdx.x;         // 0..127
    __shared__ float xr[CINN];
    __shared__ float p3[3];
    if (t < CINN) xr[t] = x[(size_t)blk * CINN + t];
    if (t < 3)    p3[t] = pos[n * 3 + t];

    g_agg[(size_t)blk * HID + t] = 0.0f;
    if (b == 0 && t == 0) g_den[n] = 0.0f;
    __syncthreads();

    float s = b1[t];
#pragma unroll
    for (int j = 0; j < 3; ++j) s += p3[j] * W1[(3 + j) * HID + t];
#pragma unroll 8
    for (int c = 0; c < CINN; ++c) s += xr[c] * W1[(6 + c) * HID + t];
    g_a_src[(size_t)blk * HID + t] = s;

    if (b == 0) {
        float d = p3[0] * W1[0 * HID + t] + p3[1] * W1[1 * HID + t] + p3[2] * W1[2 * HID + t];
        g_a_dst[(size_t)n * HID + t] = d;
    }

    float sk = bs[t];
#pragma unroll 8
    for (int c = 0; c < CINN; ++c) sk += xr[c] * Ws[c * COUT + t];
    out[(size_t)blk * COUT + t] = sk;
}

// ---------------------------------------------------------------------------
// Edge kernel (mma.sync tf32). Per block: 128 edges, 256 threads (8 warps).
//   fill:  h1[m][k] = tf32(gelu(a_dst[dst]+a_src[b,src])) packed as A frags
//   GEMM:  warp (wm,wn): D tile m[32] x n[64]; B frags via __ldg (L1-resident)
//   epi:   w_e * gelu(D + b2) -> red.global.add.v2.f32; den fused (b==0)
// SMEM: A frags 64KB + staging 1.5KB -> 2 CTAs/SM (phase overlap).
// ---------------------------------------------------------------------------
#define EDGE_SMEM (65536 + 512 + 512 + 512)
__global__ void __launch_bounds__(256, 2)
edge_kernel(const int* __restrict__ eidx, const float* __restrict__ ew,
            const float* __restrict__ b2) {
    extern __shared__ char sm[];
    uint32_t* A_s  = (uint32_t*)sm;                 // [8 g][16 s][32 l][4 slot]
    float*    b2s  = (float*)   (sm + 65536);
    float*    ews  = (float*)   (sm + 66048);
    int*      dsts = (int*)     (sm + 66560);
    const int tid = threadIdx.x;
    const int e0  = blockIdx.x * TE;
    const int b   = blockIdx.y;

    if (tid < TE) {
        b2s[tid]  = b2[tid];
        const float w = ew[e0 + tid];
        const int   d = eidx[EE + e0 + tid];
        ews[tid]  = w;
        dsts[tid] = d;
        if (b == 0) atomicAdd(&g_den[d], w);        // fused den kernel
    }

    // Fill A fragments: 2 threads per edge (k halves). Edge row m:
    // g=m>>4, r=m&15 -> lane l=(r&7)*4+(kk&3), slot=((kk>=4)<<1)+(r>=8).
    {
        const int m    = tid >> 1;
        const int half = tid & 1;
        const int sv   = eidx[e0 + m];
        const int dv   = eidx[EE + e0 + m];
        const int g    = m >> 4;
        const int r    = m & 15;
        const int lbase = (r & 7) * 4;
        const int rbit  = r >> 3;
        const float4* pd4 = (const float4*)(g_a_dst + (size_t)dv * HID);
        const float4* ps4 = (const float4*)(g_a_src + ((size_t)b * NN + sv) * HID);
#pragma unroll
        for (int si = 0; si < 8; ++si) {
            const int s = half * 8 + si;
            const float4 A0 = pd4[s * 2],     S0 = ps4[s * 2];
            const float4 A1 = pd4[s * 2 + 1], S1 = ps4[s * 2 + 1];
            float v[8] = {A0.x + S0.x, A0.y + S0.y, A0.z + S0.z, A0.w + S0.w,
                          A1.x + S1.x, A1.y + S1.y, A1.z + S1.z, A1.w + S1.w};
            uint32_t* bp = A_s + (g * 16 + s) * 128;
#pragma unroll
            for (int kk = 0; kk < 8; ++kk) {
                const int l    = lbase + (kk & 3);
                const int slot = ((kk >> 2) << 1) + rbit;
                bp[l * 4 + slot] = f2tf32(gelu_f(v[kk]));
            }
        }
    }
    __syncthreads();

    // GEMM: warp (wm, wn) -> edges [wm*32, +32), cols [wn*64, +64)
    const int lane = tid & 31;
    const int w    = tid >> 5;
    const int wm   = w & 3;
    const int wn   = w >> 2;
    float acc[2][8][4];
#pragma unroll
    for (int g = 0; g < 2; ++g)
#pragma unroll
        for (int t = 0; t < 8; ++t)
#pragma unroll
            for (int q = 0; q < 4; ++q) acc[g][t][q] = 0.0f;

    const uint2* __restrict__ Bg = (const uint2*)g_W2p;   // [t][s][l] uint2

#pragma unroll 2
    for (int s = 0; s < 16; ++s) {
        uint32_t a[2][4];
#pragma unroll
        for (int g = 0; g < 2; ++g) {
            const uint4 av = *(const uint4*)(A_s + ((wm * 2 + g) * 16 + s) * 128 + lane * 4);
            a[g][0] = av.x; a[g][1] = av.y; a[g][2] = av.z; a[g][3] = av.w;
        }
        uint32_t bf[8][2];
#pragma unroll
        for (int t = 0; t < 8; ++t) {
            const uint2 bv = __ldg(Bg + ((wn * 8 + t) * 16 + s) * 32 + lane);
            bf[t][0] = bv.x; bf[t][1] = bv.y;
        }
#pragma unroll
        for (int g = 0; g < 2; ++g)
#pragma unroll
            for (int t = 0; t < 8; ++t) mma_tf32(acc[g][t], a[g], bf[t]);
    }

    // Epilogue: D frag (r = lane>>2 (+8), c = 2*(lane&3) (+1)) -> v2 reductions
#pragma unroll
    for (int g = 0; g < 2; ++g) {
#pragma unroll
        for (int rh = 0; rh < 2; ++rh) {
            const int m   = wm * 32 + g * 16 + rh * 8 + (lane >> 2);
            const float wgt = ews[m];
            float* base = g_agg + ((size_t)b * NN + dsts[m]) * HID;
#pragma unroll
            for (int t = 0; t < 8; ++t) {
                const int c = wn * 64 + t * 8 + (lane & 3) * 2;
                const float r0 = wgt * gelu_f(acc[g][t][rh * 2 + 0] + b2s[c]);
                const float r1 = wgt * gelu_f(acc[g][t][rh * 2 + 1] + b2s[c + 1]);
                asm volatile("red.global.add.v2.f32 [%0], {%1,%2};"
                             :: "l"(base + c), "f"(r0), "f"(r1) : "memory");
            }
        }
    }
}

// ---------------------------------------------------------------------------
// Final: out[b,n] += (s[b,n] @ W3 + den[n]*b3) / (den[n] + eps)
// One block per (b,n); 128 threads; W3 stays L1-resident (64 KB).
// ---------------------------------------------------------------------------
__global__ void final_kernel(const float* __restrict__ W3, const float* __restrict__ b3,
                             float* __restrict__ out) {
    __shared__ float s_s[HID];
    const int blk = blockIdx.x;       // b*NN + n
    const int n   = blk % NN;
    const int c   = threadIdx.x;
    s_s[c] = g_agg[(size_t)blk * HID + c];
    __syncthreads();
    const float den = g_den[n];
    float acc = den * b3[c];
#pragma unroll 8
    for (int k = 0; k < HID; ++k) acc += s_s[k] * W3[k * COUT + c];
    out[(size_t)blk * COUT + c] += acc / (den + 1e-12f);
}

// ---------------------------------------------------------------------------
extern "C" void kernel_launch(void* const* d_in, const int* in_sizes, int n_in,
                              void* d_out, int out_size) {
    const float* x   = (const float*)d_in[0];
    const float* pos = (const float*)d_in[1];
    const int*   ei  = (const int*)  d_in[2];
    const float* ew  = (const float*)d_in[3];
    const float* W1  = (const float*)d_in[4];
    const float* b1  = (const float*)d_in[5];
    const float* W2  = (const float*)d_in[6];
    const float* b2  = (const float*)d_in[7];
    const float* W3  = (const float*)d_in[8];
    const float* b3  = (const float*)d_in[9];
    const float* Ws  = (const float*)d_in[10];
    const float* bs  = (const float*)d_in[11];
    float* out = (float*)d_out;

    cudaFuncSetAttribute(edge_kernel, cudaFuncAttributeMaxDynamicSharedMemorySize, EDGE_SMEM);

    w2prep_kernel<<<16 * 16 * 32 * 2 / 256, 256>>>(W2);
    precompute_kernel<<<BB * NN, HID>>>(x, pos, W1, b1, Ws, bs, out);
    edge_kernel<<<dim3(EE / TE, BB), 256, EDGE_SMEM>>>(ei, ew, b2);
    final_kernel<<<BB * NN, HID>>>(W3, b3, out);
}

// round 6
// speedup vs baseline: 1.6186x; 1.1841x over previous
#include <cuda_runtime.h>
#include <cstdint>

// Problem constants (fixed by the dataset)
#define NN   10000
#define EE   320000
#define BB   2
#define CINN 64
#define HID  128
#define COUT 128
#define TE   128          // edges per block (= M tile of the edge GEMM)
#define NROW (BB * NN)    // 20000 output rows

// Scratch (device globals: no allocations allowed)
__device__ float    g_a_dst[(size_t)NN * HID];        //  5.12 MB
__device__ float    g_a_src[(size_t)BB * NN * HID];   // 10.24 MB
__device__ float    g_agg  [(size_t)BB * NN * HID];   // 10.24 MB
__device__ float    g_den  [NN];
__device__ uint32_t g_W2p  [16 * 8 * 32 * 4];         // W2 tf32 b-frags, s-paired (64KB)
__device__ uint32_t g_W3p  [16 * 8 * 32 * 4];         // W3 tf32 b-frags, s-paired (64KB)

__device__ __forceinline__ float gelu_f(float v) {
    return 0.5f * v * (1.0f + erff(v * 0.70710678118654752440f));
}
__device__ __forceinline__ uint32_t f2tf32(float f) {
    uint32_t r; asm("cvt.rna.tf32.f32 %0, %1;" : "=r"(r) : "f"(f)); return r;
}
// mma.sync m16n8k8 tf32 (A row-major frag, B col-major frag, f32 accum)
__device__ __forceinline__ void mma_tf32(float* d, const uint32_t* a, uint32_t b0, uint32_t b1) {
    asm volatile("mma.sync.aligned.m16n8k8.row.col.f32.tf32.tf32.f32 "
                 "{%0,%1,%2,%3}, {%4,%5,%6,%7}, {%8,%9}, {%0,%1,%2,%3};"
                 : "+f"(d[0]), "+f"(d[1]), "+f"(d[2]), "+f"(d[3])
                 : "r"(a[0]), "r"(a[1]), "r"(a[2]), "r"(a[3]), "r"(b0), "r"(b1));
}

// ---------------------------------------------------------------------------
// Prep: pack a 128x128 row-major weight into tf32 B fragments, s-paired.
// uint4 entry (t, sp, l) = { b0(s=2sp), b1(s=2sp), b0(s=2sp+1), b1(s=2sp+1) }
//   b_j(s) = W[k = s*8 + j*4 + (l&3)][n = t*8 + (l>>2)]
// ---------------------------------------------------------------------------
__global__ void wprep_kernel(const float* __restrict__ W, uint32_t* __restrict__ dst) {
    const int idx = blockIdx.x * blockDim.x + threadIdx.x;   // 0..16383 words
    const int q  = idx & 3;
    const int l  = (idx >> 2) & 31;
    const int sp = (idx >> 7) & 7;
    const int t  = idx >> 10;                                 // 0..15
    const int j  = q & 1;
    const int s  = sp * 2 + (q >> 1);
    const int k  = s * 8 + j * 4 + (l & 3);
    const int n  = t * 8 + (l >> 2);
    dst[idx] = f2tf32(W[k * HID + n]);
}

// ---------------------------------------------------------------------------
// Per-node precompute (also zeroes g_agg / g_den):
//   a_dst[n]   = pos[n] @ W1[0:3]
//   a_src[b,n] = pos[n] @ W1[3:6] + x[b,n] @ W1[6:70] + b1
//   out[b,n]   = x[b,n] @ Ws + bs   (skip path; final adds)
// ---------------------------------------------------------------------------
__global__ void precompute_kernel(const float* __restrict__ x, const float* __restrict__ pos,
                                  const float* __restrict__ W1, const float* __restrict__ b1,
                                  const float* __restrict__ Ws, const float* __restrict__ bs,
                                  float* __restrict__ out) {
    const int blk = blockIdx.x;          // b*NN + n
    const int b   = blk / NN;
    const int n   = blk - b * NN;
    const int t   = threadIdx.x;         // 0..127
    __shared__ float xr[CINN];
    __shared__ float p3[3];
    if (t < CINN) xr[t] = x[(size_t)blk * CINN + t];
    if (t < 3)    p3[t] = pos[n * 3 + t];

    g_agg[(size_t)blk * HID + t] = 0.0f;
    if (b == 0 && t == 0) g_den[n] = 0.0f;
    __syncthreads();

    float s = b1[t];
#pragma unroll
    for (int j = 0; j < 3; ++j) s += p3[j] * W1[(3 + j) * HID + t];
#pragma unroll 8
    for (int c = 0; c < CINN; ++c) s += xr[c] * W1[(6 + c) * HID + t];
    g_a_src[(size_t)blk * HID + t] = s;

    if (b == 0) {
        float d = p3[0] * W1[0 * HID + t] + p3[1] * W1[1 * HID + t] + p3[2] * W1[2 * HID + t];
        g_a_dst[(size_t)n * HID + t] = d;
    }

    float sk = bs[t];
#pragma unroll 8
    for (int c = 0; c < CINN; ++c) sk += xr[c] * Ws[c * COUT + t];
    out[(size_t)blk * COUT + t] = sk;
}

// ---------------------------------------------------------------------------
// Swizzled fragment smem layout (conflict-free on BOTH write and read):
//   word(g,s,r,kk) = (g*16+s)*128 + chunk*4 + slot
//   chunk = (r&7)*4 + ((kk&3) ^ (((r&7)>>1)&3))       [XOR bank swizzle]
//   slot  = ((kk>>2)*2 + (r>>3)) ^ ((s>>3)*2)          [s-half slot swap]
// Writer (fixed si,kk): 32 lanes -> 32 distinct banks (verified by enum).
// Reader: lane l reads uint4 at chunk_r = (l>>2)*4 + ((l&3)^(((l>>2)>>1)&3));
//   s<8: a={x,y,z,w}; s>=8: a={z,w,x,y}.
// ---------------------------------------------------------------------------
__device__ __forceinline__ int frag_chunk_r(int lane) {
    return (lane >> 2) * 4 + ((lane & 3) ^ (((lane >> 2) >> 1) & 3));
}

// ---------------------------------------------------------------------------
// Edge kernel (mma.sync tf32). Per block: 128 edges, 256 threads (8 warps).
// SMEM: A frags 64KB + staging -> 2 CTAs/SM.
// ---------------------------------------------------------------------------
#define EDGE_SMEM (65536 + 512 + 512 + 512)
__global__ void __launch_bounds__(256, 2)
edge_kernel(const int* __restrict__ eidx, const float* __restrict__ ew,
            const float* __restrict__ b2) {
    extern __shared__ char sm[];
    uint32_t* A_s  = (uint32_t*)sm;                 // [8 g][16 s][128 words]
    float*    b2s  = (float*)   (sm + 65536);
    float*    ews  = (float*)   (sm + 66048);
    int*      dsts = (int*)     (sm + 66560);
    const int tid = threadIdx.x;
    const int e0  = blockIdx.x * TE;
    const int b   = blockIdx.y;

    if (tid < TE) {
        b2s[tid]  = b2[tid];
        const float w = ew[e0 + tid];
        const int   d = eidx[EE + e0 + tid];
        ews[tid]  = w;
        dsts[tid] = d;
        if (b == 0) atomicAdd(&g_den[d], w);        // fused den kernel
    }

    // Fill A fragments (swizzled, conflict-free). 2 threads per edge.
    {
        const int m    = tid >> 1;                  // edge row 0..127
        const int half = tid & 1;
        const int sv   = eidx[e0 + m];
        const int dv   = eidx[EE + e0 + m];
        const int g    = m >> 4;                    // == warp id
        const int r    = m & 15;
        const int r7   = r & 7;
        const int rh   = r >> 3;
        const int swz  = (r7 >> 1) & 3;
        const int sswap = half * 2;                 // (s>>3)*2
        const float4* pd4 = (const float4*)(g_a_dst + (size_t)dv * HID);
        const float4* ps4 = (const float4*)(g_a_src + ((size_t)b * NN + sv) * HID);
#pragma unroll
        for (int si = 0; si < 8; ++si) {
            const int s = half * 8 + si;
            const float4 A0 = pd4[s * 2],     S0 = ps4[s * 2];
            const float4 A1 = pd4[s * 2 + 1], S1 = ps4[s * 2 + 1];
            const float v[8] = {A0.x + S0.x, A0.y + S0.y, A0.z + S0.z, A0.w + S0.w,
                                A1.x + S1.x, A1.y + S1.y, A1.z + S1.z, A1.w + S1.w};
            uint32_t* rowp = A_s + (g * 16 + s) * 128;
#pragma unroll
            for (int kk = 0; kk < 8; ++kk) {
                const int chunk = r7 * 4 + ((kk & 3) ^ swz);
                const int slot  = (((kk >> 2) << 1) + rh) ^ sswap;
                rowp[chunk * 4 + slot] = f2tf32(gelu_f(v[kk]));
            }
        }
    }
    __syncthreads();

    // GEMM: warp (wm, wn) -> edges [wm*32,+32), cols [wn*64,+64)
    const int lane = tid & 31;
    const int w    = tid >> 5;
    const int wm   = w & 3;
    const int wn   = w >> 2;
    const int ckr  = frag_chunk_r(lane) * 4;
    float acc[2][8][4];
#pragma unroll
    for (int g = 0; g < 2; ++g)
#pragma unroll
        for (int t = 0; t < 8; ++t)
#pragma unroll
            for (int q = 0; q < 4; ++q) acc[g][t][q] = 0.0f;

    const uint4* __restrict__ Bg4 = (const uint4*)g_W2p;

#pragma unroll
    for (int sp = 0; sp < 8; ++sp) {
        const int s0 = sp * 2;
        const bool hi = (s0 >= 8);                  // pairs never straddle s=8
        uint32_t a[2][2][4];
#pragma unroll
        for (int gg = 0; gg < 2; ++gg) {
            const int g = wm * 2 + gg;
            const uint4 v0 = *(const uint4*)(A_s + (g * 16 + s0) * 128 + ckr);
            const uint4 v1 = *(const uint4*)(A_s + (g * 16 + s0 + 1) * 128 + ckr);
            if (!hi) {
                a[gg][0][0] = v0.x; a[gg][0][1] = v0.y; a[gg][0][2] = v0.z; a[gg][0][3] = v0.w;
                a[gg][1][0] = v1.x; a[gg][1][1] = v1.y; a[gg][1][2] = v1.z; a[gg][1][3] = v1.w;
            } else {
                a[gg][0][0] = v0.z; a[gg][0][1] = v0.w; a[gg][0][2] = v0.x; a[gg][0][3] = v0.y;
                a[gg][1][0] = v1.z; a[gg][1][1] = v1.w; a[gg][1][2] = v1.x; a[gg][1][3] = v1.y;
            }
        }
#pragma unroll
        for (int t = 0; t < 8; ++t) {
            const uint4 bv = __ldg(Bg4 + ((wn * 8 + t) * 8 + sp) * 32 + lane);
            mma_tf32(acc[0][t], a[0][0], bv.x, bv.y);
            mma_tf32(acc[1][t], a[1][0], bv.x, bv.y);
            mma_tf32(acc[0][t], a[0][1], bv.z, bv.w);
            mma_tf32(acc[1][t], a[1][1], bv.z, bv.w);
        }
    }

    // Epilogue: D frag (r = lane>>2 (+8), c = 2*(lane&3) (+1)) -> v2 reductions
#pragma unroll
    for (int g = 0; g < 2; ++g) {
#pragma unroll
        for (int rh = 0; rh < 2; ++rh) {
            const int m   = wm * 32 + g * 16 + rh * 8 + (lane >> 2);
            const float wgt = ews[m];
            float* base = g_agg + ((size_t)b * NN + dsts[m]) * HID;
#pragma unroll
            for (int t = 0; t < 8; ++t) {
                const int c = wn * 64 + t * 8 + (lane & 3) * 2;
                const float r0 = wgt * gelu_f(acc[g][t][rh * 2 + 0] + b2s[c]);
                const float r1 = wgt * gelu_f(acc[g][t][rh * 2 + 1] + b2s[c + 1]);
                asm volatile("red.global.add.v2.f32 [%0], {%1,%2};"
                             :: "l"(base + c), "f"(r0), "f"(r1) : "memory");
            }
        }
    }
}

// ---------------------------------------------------------------------------
// Final kernel (mma.sync tf32): out[row] += (agg[row] @ W3 + den*b3)/(den+eps)
// 128 rows per block, 256 threads, same swizzled fragment machinery.
// ---------------------------------------------------------------------------
#define FIN_SMEM (65536 + 512 + 512)
__global__ void __launch_bounds__(256, 2)
final_kernel(const float* __restrict__ b3, float* __restrict__ out) {
    extern __shared__ char sm[];
    uint32_t* A_s  = (uint32_t*)sm;                 // [8 g][16 s][128 words]
    float*    b3s  = (float*)(sm + 65536);
    float*    dens = (float*)(sm + 66048);
    const int tid = threadIdx.x;
    const int r0  = blockIdx.x * 128;

    if (tid < 128) {
        b3s[tid] = b3[tid];
        const int row = r0 + tid;
        dens[tid] = (row < NROW) ? g_den[row % NN] : 0.0f;
    }

    // Fill A fragments from g_agg rows (no gather, no gelu)
    {
        const int m    = tid >> 1;
        const int half = tid & 1;
        const int row  = r0 + m;
        const bool ok  = (row < NROW);
        const int g    = m >> 4;
        const int r    = m & 15;
        const int r7   = r & 7;
        const int rh   = r >> 3;
        const int swz  = (r7 >> 1) & 3;
        const int sswap = half * 2;
        const float4* pa4 = (const float4*)(g_agg + (size_t)(ok ? row : 0) * HID);
#pragma unroll
        for (int si = 0; si < 8; ++si) {
            const int s = half * 8 + si;
            float4 A0 = pa4[s * 2], A1 = pa4[s * 2 + 1];
            if (!ok) { A0 = make_float4(0, 0, 0, 0); A1 = A0; }
            const float v[8] = {A0.x, A0.y, A0.z, A0.w, A1.x, A1.y, A1.z, A1.w};
            uint32_t* rowp = A_s + (g * 16 + s) * 128;
#pragma unroll
            for (int kk = 0; kk < 8; ++kk) {
                const int chunk = r7 * 4 + ((kk & 3) ^ swz);
                const int slot  = (((kk >> 2) << 1) + rh) ^ sswap;
                rowp[chunk * 4 + slot] = f2tf32(v[kk]);
            }
        }
    }
    __syncthreads();

    const int lane = tid & 31;
    const int w    = tid >> 5;
    const int wm   = w & 3;
    const int wn   = w >> 2;
    const int ckr  = frag_chunk_r(lane) * 4;
    float acc[2][8][4];
#pragma unroll
    for (int g = 0; g < 2; ++g)
#pragma unroll
        for (int t = 0; t < 8; ++t)
#pragma unroll
            for (int q = 0; q < 4; ++q) acc[g][t][q] = 0.0f;

    const uint4* __restrict__ Bg4 = (const uint4*)g_W3p;

#pragma unroll
    for (int sp = 0; sp < 8; ++sp) {
        const int s0 = sp * 2;
        const bool hi = (s0 >= 8);
        uint32_t a[2][2][4];
#pragma unroll
        for (int gg = 0; gg < 2; ++gg) {
            const int g = wm * 2 + gg;
            const uint4 v0 = *(const uint4*)(A_s + (g * 16 + s0) * 128 + ckr);
            const uint4 v1 = *(const uint4*)(A_s + (g * 16 + s0 + 1) * 128 + ckr);
            if (!hi) {
                a[gg][0][0] = v0.x; a[gg][0][1] = v0.y; a[gg][0][2] = v0.z; a[gg][0][3] = v0.w;
                a[gg][1][0] = v1.x; a[gg][1][1] = v1.y; a[gg][1][2] = v1.z; a[gg][1][3] = v1.w;
            } else {
                a[gg][0][0] = v0.z; a[gg][0][1] = v0.w; a[gg][0][2] = v0.x; a[gg][0][3] = v0.y;
                a[gg][1][0] = v1.z; a[gg][1][1] = v1.w; a[gg][1][2] = v1.x; a[gg][1][3] = v1.y;
            }
        }
#pragma unroll
        for (int t = 0; t < 8; ++t) {
            const uint4 bv = __ldg(Bg4 + ((wn * 8 + t) * 8 + sp) * 32 + lane);
            mma_tf32(acc[0][t], a[0][0], bv.x, bv.y);
            mma_tf32(acc[1][t], a[1][0], bv.x, bv.y);
            mma_tf32(acc[0][t], a[0][1], bv.z, bv.w);
            mma_tf32(acc[1][t], a[1][1], bv.z, bv.w);
        }
    }

    // Epilogue: out += (acc + den*b3)/(den+eps), plain read-modify-write
#pragma unroll
    for (int g = 0; g < 2; ++g) {
#pragma unroll
        for (int rh = 0; rh < 2; ++rh) {
            const int m   = wm * 32 + g * 16 + rh * 8 + (lane >> 2);
            const int row = r0 + m;
            if (row < NROW) {
                const float den = dens[m];
                const float inv = 1.0f / (den + 1e-12f);
                float* op = out + (size_t)row * COUT;
#pragma unroll
                for (int t = 0; t < 8; ++t) {
                    const int c = wn * 64 + t * 8 + (lane & 3) * 2;
                    float2 o = *(float2*)(op + c);
                    o.x += (acc[g][t][rh * 2 + 0] + den * b3s[c]) * inv;
                    o.y += (acc[g][t][rh * 2 + 1] + den * b3s[c + 1]) * inv;
                    *(float2*)(op + c) = o;
                }
            }
        }
    }
}

// ---------------------------------------------------------------------------
extern "C" void kernel_launch(void* const* d_in, const int* in_sizes, int n_in,
                              void* d_out, int out_size) {
    const float* x   = (const float*)d_in[0];
    const float* pos = (const float*)d_in[1];
    const int*   ei  = (const int*)  d_in[2];
    const float* ew  = (const float*)d_in[3];
    const float* W1  = (const float*)d_in[4];
    const float* b1  = (const float*)d_in[5];
    const float* W2  = (const float*)d_in[6];
    const float* b2  = (const float*)d_in[7];
    const float* W3  = (const float*)d_in[8];
    const float* b3  = (const float*)d_in[9];
    const float* Ws  = (const float*)d_in[10];
    const float* bs  = (const float*)d_in[11];
    float* out = (float*)d_out;

    uint32_t* w2p; cudaGetSymbolAddress((void**)&w2p, g_W2p);
    uint32_t* w3p; cudaGetSymbolAddress((void**)&w3p, g_W3p);

    cudaFuncSetAttribute(edge_kernel,  cudaFuncAttributeMaxDynamicSharedMemorySize, EDGE_SMEM);
    cudaFuncSetAttribute(final_kernel, cudaFuncAttributeMaxDynamicSharedMemorySize, FIN_SMEM);

    wprep_kernel<<<64, 256>>>(W2, w2p);
    wprep_kernel<<<64, 256>>>(W3, w3p);
    precompute_kernel<<<NROW, HID>>>(x, pos, W1, b1, Ws, bs, out);
    edge_kernel<<<dim3(EE / TE, BB), 256, EDGE_SMEM>>>(ei, ew, b2);
    final_kernel<<<(NROW + 127) / 128, 256, FIN_SMEM>>>(b3, out);
}

// round 7
// speedup vs baseline: 1.7965x; 1.1099x over previous
#include <cuda_runtime.h>
#include <cstdint>

// Problem constants (fixed by the dataset)
#define NN   10000
#define EE   320000
#define BB   2
#define CINN 64
#define HID  128
#define COUT 128
#define TE   128          // edges per block (= M tile of the edge GEMM)
#define NROW (BB * NN)    // 20000 output rows

// Scratch (device globals: no allocations allowed)
__device__ float    g_a_dst[(size_t)NN * HID];        //  5.12 MB
__device__ float    g_a_src[(size_t)BB * NN * HID];   // 10.24 MB
__device__ float    g_agg  [(size_t)BB * NN * HID];   // 10.24 MB
__device__ float    g_den  [NN];
__device__ uint32_t g_W2p  [16 * 8 * 32 * 4];         // W2 tf32 b-frags, s-paired (64KB)
__device__ uint32_t g_W3p  [16 * 8 * 32 * 4];         // W3 tf32 b-frags, s-paired (64KB)

__device__ __forceinline__ float gelu_f(float v) {
    return 0.5f * v * (1.0f + erff(v * 0.70710678118654752440f));
}
__device__ __forceinline__ uint32_t f2tf32(float f) {
    uint32_t r; asm("cvt.rna.tf32.f32 %0, %1;" : "=r"(r) : "f"(f)); return r;
}
// mma.sync m16n8k8 tf32 (A row-major frag, B col-major frag, f32 accum)
__device__ __forceinline__ void mma_tf32(float* d, const uint32_t* a, uint32_t b0, uint32_t b1) {
    asm volatile("mma.sync.aligned.m16n8k8.row.col.f32.tf32.tf32.f32 "
                 "{%0,%1,%2,%3}, {%4,%5,%6,%7}, {%8,%9}, {%0,%1,%2,%3};"
                 : "+f"(d[0]), "+f"(d[1]), "+f"(d[2]), "+f"(d[3])
                 : "r"(a[0]), "r"(a[1]), "r"(a[2]), "r"(a[3]), "r"(b0), "r"(b1));
}

// ---------------------------------------------------------------------------
// Prep: pack a 128x128 row-major weight into tf32 B fragments, s-paired.
// uint4 entry (t, sp, l) = { b0(s=2sp), b1(s=2sp), b0(s=2sp+1), b1(s=2sp+1) }
//   b_j(s) = W[k = s*8 + j*4 + (l&3)][n = t*8 + (l>>2)]
// ---------------------------------------------------------------------------
__global__ void wprep_kernel(const float* __restrict__ W, uint32_t* __restrict__ dst) {
    const int idx = blockIdx.x * blockDim.x + threadIdx.x;   // 0..16383 words
    const int q  = idx & 3;
    const int l  = (idx >> 2) & 31;
    const int sp = (idx >> 7) & 7;
    const int t  = idx >> 10;                                 // 0..15
    const int j  = q & 1;
    const int s  = sp * 2 + (q >> 1);
    const int k  = s * 8 + j * 4 + (l & 3);
    const int n  = t * 8 + (l >> 2);
    dst[idx] = f2tf32(W[k * HID + n]);
}

// ---------------------------------------------------------------------------
// Per-node precompute (also zeroes g_agg / g_den):
//   a_dst[n]   = pos[n] @ W1[0:3]
//   a_src[b,n] = pos[n] @ W1[3:6] + x[b,n] @ W1[6:70] + b1
//   out[b,n]   = x[b,n] @ Ws + bs   (skip path; final adds)
// ---------------------------------------------------------------------------
__global__ void precompute_kernel(const float* __restrict__ x, const float* __restrict__ pos,
                                  const float* __restrict__ W1, const float* __restrict__ b1,
                                  const float* __restrict__ Ws, const float* __restrict__ bs,
                                  float* __restrict__ out) {
    const int blk = blockIdx.x;          // b*NN + n
    const int b   = blk / NN;
    const int n   = blk - b * NN;
    const int t   = threadIdx.x;         // 0..127
    __shared__ float xr[CINN];
    __shared__ float p3[3];
    if (t < CINN) xr[t] = x[(size_t)blk * CINN + t];
    if (t < 3)    p3[t] = pos[n * 3 + t];

    g_agg[(size_t)blk * HID + t] = 0.0f;
    if (b == 0 && t == 0) g_den[n] = 0.0f;
    __syncthreads();

    float s = b1[t];
#pragma unroll
    for (int j = 0; j < 3; ++j) s += p3[j] * W1[(3 + j) * HID + t];
#pragma unroll 8
    for (int c = 0; c < CINN; ++c) s += xr[c] * W1[(6 + c) * HID + t];
    g_a_src[(size_t)blk * HID + t] = s;

    if (b == 0) {
        float d = p3[0] * W1[0 * HID + t] + p3[1] * W1[1 * HID + t] + p3[2] * W1[2 * HID + t];
        g_a_dst[(size_t)n * HID + t] = d;
    }

    float sk = bs[t];
#pragma unroll 8
    for (int c = 0; c < CINN; ++c) sk += xr[c] * Ws[c * COUT + t];
    out[(size_t)blk * COUT + t] = sk;
}

// ---------------------------------------------------------------------------
// Swizzled fragment smem layout (conflict-free write AND read, sector-paired):
//   word(g,s,r,kk) = (g*16+s)*128 + chunk*4 + slot
//     chunk = (r&7)*4 + ((kk&3) ^ (((r&7)>>1)&3))   [XOR bank swizzle]
//     slot  = (r>>3)*2 + (kk>>2)
// Fill: 2 threads/edge, thread h = khalf h; lane pairs read ADJACENT 16B of
// the same row (full 32B sectors). Writer banks (fixed s,j):
//   16(r7&1) + 4(j^((r7>>1)&3)) + 2rh + h  -> all 32 distinct.
// Reader lane l: uint4 at chunk_r(l)*4; a = {v.x, v.z, v.y, v.w}.
// ---------------------------------------------------------------------------
__device__ __forceinline__ int frag_chunk_r(int lane) {
    return (lane >> 2) * 4 + ((lane & 3) ^ (((lane >> 2) >> 1) & 3));
}

// ---------------------------------------------------------------------------
// Edge kernel (mma.sync tf32). Per block: 128 edges, 256 threads (8 warps).
// SMEM: A frags 64KB + staging -> 2 CTAs/SM.
// ---------------------------------------------------------------------------
#define EDGE_SMEM (65536 + 512 + 512 + 512)
__global__ void __launch_bounds__(256, 2)
edge_kernel(const int* __restrict__ eidx, const float* __restrict__ ew,
            const float* __restrict__ b2) {
    extern __shared__ char sm[];
    uint32_t* A_s  = (uint32_t*)sm;                 // [8 g][16 s][128 words]
    float*    b2s  = (float*)   (sm + 65536);
    float*    ews  = (float*)   (sm + 66048);
    int*      dsts = (int*)     (sm + 66560);
    const int tid = threadIdx.x;
    const int e0  = blockIdx.x * TE;
    const int b   = blockIdx.y;

    if (tid < TE) {
        b2s[tid]  = b2[tid];
        const float w = ew[e0 + tid];
        const int   d = eidx[EE + e0 + tid];
        ews[tid]  = w;
        dsts[tid] = d;
        if (b == 0) atomicAdd(&g_den[d], w);        // fused den kernel
    }

    // Fill A fragments (swizzled, conflict-free, sector-paired gathers).
    {
        const int m  = tid >> 1;                    // edge row 0..127
        const int h  = tid & 1;                     // khalf owned by this thread
        const int sv = eidx[e0 + m];
        const int dv = eidx[EE + e0 + m];
        const int g  = m >> 4;
        const int r  = m & 15;
        const int r7 = r & 7;
        const int rh = r >> 3;
        const int swz = (r7 >> 1) & 3;
        int offs[4];
#pragma unroll
        for (int j = 0; j < 4; ++j)
            offs[j] = (r7 * 4 + (j ^ swz)) * 4 + rh * 2 + h;
        const float4* pd4 = (const float4*)(g_a_dst + (size_t)dv * HID);
        const float4* ps4 = (const float4*)(g_a_src + ((size_t)b * NN + sv) * HID);
#pragma unroll
        for (int i = 0; i < 16; ++i) {              // i = s step
            const float4 A0 = pd4[2 * i + h];
            const float4 S0 = ps4[2 * i + h];
            uint32_t* rowp = A_s + (g * 16 + i) * 128;
            rowp[offs[0]] = f2tf32(gelu_f(A0.x + S0.x));
            rowp[offs[1]] = f2tf32(gelu_f(A0.y + S0.y));
            rowp[offs[2]] = f2tf32(gelu_f(A0.z + S0.z));
            rowp[offs[3]] = f2tf32(gelu_f(A0.w + S0.w));
        }
    }
    __syncthreads();

    // GEMM: warp (wm, wn) -> edges [wm*32,+32), cols [wn*64,+64)
    const int lane = tid & 31;
    const int w    = tid >> 5;
    const int wm   = w & 3;
    const int wn   = w >> 2;
    const int ckr  = frag_chunk_r(lane) * 4;
    float acc[2][8][4];
#pragma unroll
    for (int g = 0; g < 2; ++g)
#pragma unroll
        for (int t = 0; t < 8; ++t)
#pragma unroll
            for (int q = 0; q < 4; ++q) acc[g][t][q] = 0.0f;

    const uint4* __restrict__ Bg4 = (const uint4*)g_W2p;

#pragma unroll
    for (int sp = 0; sp < 8; ++sp) {
        const int s0 = sp * 2;
        uint32_t a[2][2][4];
#pragma unroll
        for (int gg = 0; gg < 2; ++gg) {
            const int g = wm * 2 + gg;
            const uint4 v0 = *(const uint4*)(A_s + (g * 16 + s0) * 128 + ckr);
            const uint4 v1 = *(const uint4*)(A_s + (g * 16 + s0 + 1) * 128 + ckr);
            a[gg][0][0] = v0.x; a[gg][0][1] = v0.z; a[gg][0][2] = v0.y; a[gg][0][3] = v0.w;
            a[gg][1][0] = v1.x; a[gg][1][1] = v1.z; a[gg][1][2] = v1.y; a[gg][1][3] = v1.w;
        }
#pragma unroll
        for (int t = 0; t < 8; ++t) {
            const uint4 bv = __ldg(Bg4 + ((wn * 8 + t) * 8 + sp) * 32 + lane);
            mma_tf32(acc[0][t], a[0][0], bv.x, bv.y);
            mma_tf32(acc[1][t], a[1][0], bv.x, bv.y);
            mma_tf32(acc[0][t], a[0][1], bv.z, bv.w);
            mma_tf32(acc[1][t], a[1][1], bv.z, bv.w);
        }
    }

    // Epilogue: D frag (r = lane>>2 (+8), c = 2*(lane&3) (+1)) -> v2 reductions
    float b2v[8][2];
#pragma unroll
    for (int t = 0; t < 8; ++t) {
        const int c = wn * 64 + t * 8 + (lane & 3) * 2;
        b2v[t][0] = b2s[c];
        b2v[t][1] = b2s[c + 1];
    }
#pragma unroll
    for (int g = 0; g < 2; ++g) {
#pragma unroll
        for (int rh = 0; rh < 2; ++rh) {
            const int m   = wm * 32 + g * 16 + rh * 8 + (lane >> 2);
            const float wgt = ews[m];
            float* base = g_agg + ((size_t)b * NN + dsts[m]) * HID;
#pragma unroll
            for (int t = 0; t < 8; ++t) {
                const int c = wn * 64 + t * 8 + (lane & 3) * 2;
                const float r0 = wgt * gelu_f(acc[g][t][rh * 2 + 0] + b2v[t][0]);
                const float r1 = wgt * gelu_f(acc[g][t][rh * 2 + 1] + b2v[t][1]);
                asm volatile("red.global.add.v2.f32 [%0], {%1,%2};"
                             :: "l"(base + c), "f"(r0), "f"(r1) : "memory");
            }
        }
    }
}

// ---------------------------------------------------------------------------
// Final kernel (mma.sync tf32): out[row] += (agg[row] @ W3 + den*b3)/(den+eps)
// 128 rows per block, 256 threads, same fragment machinery (no gather/gelu).
// ---------------------------------------------------------------------------
#define FIN_SMEM (65536 + 512 + 512)
__global__ void __launch_bounds__(256, 2)
final_kernel(const float* __restrict__ b3, float* __restrict__ out) {
    extern __shared__ char sm[];
    uint32_t* A_s  = (uint32_t*)sm;                 // [8 g][16 s][128 words]
    float*    b3s  = (float*)(sm + 65536);
    float*    dens = (float*)(sm + 66048);
    const int tid = threadIdx.x;
    const int r0  = blockIdx.x * 128;

    if (tid < 128) {
        b3s[tid] = b3[tid];
        const int row = r0 + tid;
        dens[tid] = (row < NROW) ? g_den[row % NN] : 0.0f;
    }

    // Fill A fragments from g_agg rows
    {
        const int m   = tid >> 1;
        const int h   = tid & 1;
        const int row = r0 + m;
        const bool ok = (row < NROW);
        const int g  = m >> 4;
        const int r  = m & 15;
        const int r7 = r & 7;
        const int rh = r >> 3;
        const int swz = (r7 >> 1) & 3;
        int offs[4];
#pragma unroll
        for (int j = 0; j < 4; ++j)
            offs[j] = (r7 * 4 + (j ^ swz)) * 4 + rh * 2 + h;
        const float4* pa4 = (const float4*)(g_agg + (size_t)(ok ? row : 0) * HID);
#pragma unroll
        for (int i = 0; i < 16; ++i) {
            float4 A0 = pa4[2 * i + h];
            if (!ok) A0 = make_float4(0, 0, 0, 0);
            uint32_t* rowp = A_s + (g * 16 + i) * 128;
            rowp[offs[0]] = f2tf32(A0.x);
            rowp[offs[1]] = f2tf32(A0.y);
            rowp[offs[2]] = f2tf32(A0.z);
            rowp[offs[3]] = f2tf32(A0.w);
        }
    }
    __syncthreads();

    const int lane = tid & 31;
    const int w    = tid >> 5;
    const int wm   = w & 3;
    const int wn   = w >> 2;
    const int ckr  = frag_chunk_r(lane) * 4;
    float acc[2][8][4];
#pragma unroll
    for (int g = 0; g < 2; ++g)
#pragma unroll
        for (int t = 0; t < 8; ++t)
#pragma unroll
            for (int q = 0; q < 4; ++q) acc[g][t][q] = 0.0f;

    const uint4* __restrict__ Bg4 = (const uint4*)g_W3p;

#pragma unroll
    for (int sp = 0; sp < 8; ++sp) {
        const int s0 = sp * 2;
        uint32_t a[2][2][4];
#pragma unroll
        for (int gg = 0; gg < 2; ++gg) {
            const int g = wm * 2 + gg;
            const uint4 v0 = *(const uint4*)(A_s + (g * 16 + s0) * 128 + ckr);
            const uint4 v1 = *(const uint4*)(A_s + (g * 16 + s0 + 1) * 128 + ckr);
            a[gg][0][0] = v0.x; a[gg][0][1] = v0.z; a[gg][0][2] = v0.y; a[gg][0][3] = v0.w;
            a[gg][1][0] = v1.x; a[gg][1][1] = v1.z; a[gg][1][2] = v1.y; a[gg][1][3] = v1.w;
        }
#pragma unroll
        for (int t = 0; t < 8; ++t) {
            const uint4 bv = __ldg(Bg4 + ((wn * 8 + t) * 8 + sp) * 32 + lane);
            mma_tf32(acc[0][t], a[0][0], bv.x, bv.y);
            mma_tf32(acc[1][t], a[1][0], bv.x, bv.y);
            mma_tf32(acc[0][t], a[0][1], bv.z, bv.w);
            mma_tf32(acc[1][t], a[1][1], bv.z, bv.w);
        }
    }

    // Epilogue: out += (acc + den*b3)/(den+eps)
#pragma unroll
    for (int g = 0; g < 2; ++g) {
#pragma unroll
        for (int rh = 0; rh < 2; ++rh) {
            const int m   = wm * 32 + g * 16 + rh * 8 + (lane >> 2);
            const int row = r0 + m;
            if (row < NROW) {
                const float den = dens[m];
                const float inv = 1.0f / (den + 1e-12f);
                float* op = out + (size_t)row * COUT;
#pragma unroll
                for (int t = 0; t < 8; ++t) {
                    const int c = wn * 64 + t * 8 + (lane & 3) * 2;
                    float2 o = *(float2*)(op + c);
                    o.x += (acc[g][t][rh * 2 + 0] + den * b3s[c]) * inv;
                    o.y += (acc[g][t][rh * 2 + 1] + den * b3s[c + 1]) * inv;
                    *(float2*)(op + c) = o;
                }
            }
        }
    }
}

// ---------------------------------------------------------------------------
extern "C" void kernel_launch(void* const* d_in, const int* in_sizes, int n_in,
                              void* d_out, int out_size) {
    const float* x   = (const float*)d_in[0];
    const float* pos = (const float*)d_in[1];
    const int*   ei  = (const int*)  d_in[2];
    const float* ew  = (const float*)d_in[3];
    const float* W1  = (const float*)d_in[4];
    const float* b1  = (const float*)d_in[5];
    const float* W2  = (const float*)d_in[6];
    const float* b2  = (const float*)d_in[7];
    const float* W3  = (const float*)d_in[8];
    const float* b3  = (const float*)d_in[9];
    const float* Ws  = (const float*)d_in[10];
    const float* bs  = (const float*)d_in[11];
    float* out = (float*)d_out;

    uint32_t* w2p; cudaGetSymbolAddress((void**)&w2p, g_W2p);
    uint32_t* w3p; cudaGetSymbolAddress((void**)&w3p, g_W3p);

    cudaFuncSetAttribute(edge_kernel,  cudaFuncAttributeMaxDynamicSharedMemorySize, EDGE_SMEM);
    cudaFuncSetAttribute(final_kernel, cudaFuncAttributeMaxDynamicSharedMemorySize, FIN_SMEM);

    wprep_kernel<<<64, 256>>>(W2, w2p);
    wprep_kernel<<<64, 256>>>(W3, w3p);
    precompute_kernel<<<NROW, HID>>>(x, pos, W1, b1, Ws, bs, out);
    edge_kernel<<<dim3(EE / TE, BB), 256, EDGE_SMEM>>>(ei, ew, b2);
    final_kernel<<<(NROW + 127) / 128, 256, FIN_SMEM>>>(b3, out);
}